// round 1
// baseline (speedup 1.0000x reference)
#include <cuda_runtime.h>
#include <cstdint>
#include <cstddef>

// ---------------- problem constants ----------------
#define B_    32
#define NTOK  3136          // 56*56
#define C_    512
#define NH    8
#define HD    64
#define S_    49            // 7*7 window
#define G_    64            // 8*8 windows
#define M_    (B_*G_*S_)    // 100352 rows (divisible by 128)
#define QKVN  1536
#define SCALE_ 0.125f       // 64^-0.5
// log2(10000)/16
#define L2T_OVER16 0.8304820237218406f

// ---------------- scratch ----------------
__device__ float g_qkv[(size_t)M_ * QKVN];   // [M][3*NH*HD] in (b,g,s) row order
__device__ float g_att[(size_t)M_ * C_];     // attention output in (b,n) row order

// row r (in b,g,s order) -> x row offset (b,n)
__device__ __forceinline__ size_t gather_row_off(int r) {
    int b   = r / (G_ * S_);
    int rem = r - b * (G_ * S_);
    int g   = rem / S_;
    int s   = rem - g * S_;
    int sy  = s / 7;
    int sx  = s - sy * 7;
    int n   = ((g >> 3) * 7 + sy) * 56 + (g & 7) * 7 + sx;
    return ((size_t)b * NTOK + n) * C_;
}

// ---------------- 128x128x8 SGEMM, 8x8 microtile, 256 threads ----------------
// C[r][d] = sum_k A[r][k] * W[d][k]  (+bias[d])
template <int NCOLS, bool GATHER, bool BIAS>
__global__ __launch_bounds__(256) void sgemm128(
    const float* __restrict__ A, const float* __restrict__ W,
    const float* __restrict__ bias, float* __restrict__ Cc)
{
    __shared__ float As[8][128];
    __shared__ float Bs[8][128];

    const int tid = threadIdx.x;
    const int bm  = blockIdx.x * 128;
    const int bn  = blockIdx.y * 128;

    const int lr = tid >> 1;           // tile row this thread loads (A and W)
    const int lk = (tid & 1) * 4;      // k segment

    const float* arow;
    if (GATHER) arow = A + gather_row_off(bm + lr);
    else        arow = A + (size_t)(bm + lr) * C_;
    const float* brow = W + (size_t)(bn + lr) * C_;

    const int tr = (tid >> 4) * 8;     // microtile row offset
    const int tc = (tid & 15) * 8;     // microtile col offset

    float acc[8][8];
    #pragma unroll
    for (int i = 0; i < 8; i++)
        #pragma unroll
        for (int j = 0; j < 8; j++) acc[i][j] = 0.0f;

    for (int k0 = 0; k0 < C_; k0 += 8) {
        float4 av = *(const float4*)(arow + k0 + lk);
        float4 bv = *(const float4*)(brow + k0 + lk);
        As[lk + 0][lr] = av.x; As[lk + 1][lr] = av.y;
        As[lk + 2][lr] = av.z; As[lk + 3][lr] = av.w;
        Bs[lk + 0][lr] = bv.x; Bs[lk + 1][lr] = bv.y;
        Bs[lk + 2][lr] = bv.z; Bs[lk + 3][lr] = bv.w;
        __syncthreads();

        #pragma unroll
        for (int kk = 0; kk < 8; kk++) {
            float4 a0 = *(const float4*)&As[kk][tr];
            float4 a1 = *(const float4*)&As[kk][tr + 4];
            float4 b0 = *(const float4*)&Bs[kk][tc];
            float4 b1 = *(const float4*)&Bs[kk][tc + 4];
            float a[8] = {a0.x, a0.y, a0.z, a0.w, a1.x, a1.y, a1.z, a1.w};
            float b[8] = {b0.x, b0.y, b0.z, b0.w, b1.x, b1.y, b1.z, b1.w};
            #pragma unroll
            for (int i = 0; i < 8; i++)
                #pragma unroll
                for (int j = 0; j < 8; j++)
                    acc[i][j] = fmaf(a[i], b[j], acc[i][j]);
        }
        __syncthreads();
    }

    float bvals[8];
    #pragma unroll
    for (int j = 0; j < 8; j++) bvals[j] = BIAS ? bias[bn + tc + j] : 0.0f;

    #pragma unroll
    for (int i = 0; i < 8; i++) {
        float* crow = Cc + (size_t)(bm + tr + i) * NCOLS + bn + tc;
        float4 o0, o1;
        o0.x = acc[i][0] + bvals[0]; o0.y = acc[i][1] + bvals[1];
        o0.z = acc[i][2] + bvals[2]; o0.w = acc[i][3] + bvals[3];
        o1.x = acc[i][4] + bvals[4]; o1.y = acc[i][5] + bvals[5];
        o1.z = acc[i][6] + bvals[6]; o1.w = acc[i][7] + bvals[7];
        *(float4*)(crow)     = o0;
        *(float4*)(crow + 4) = o1;
    }
}

// ---------------- 2D RoPE on q and k ----------------
// one thread per complex pair; layout g_qkv[r][which*512 + h*64 + 2m {,+1}]
__global__ __launch_bounds__(256) void rope_kernel() {
    size_t t = (size_t)blockIdx.x * 256 + threadIdx.x;   // exactly M_*512 threads
    int m     = (int)(t & 31);
    int h     = (int)((t >> 5) & 7);
    int which = (int)((t >> 8) & 1);
    size_t r  = t >> 9;
    int s     = (int)(r % S_);

    int   j    = m >> 1;
    float pos  = (m & 1) ? (float)(s / 7) : (float)(s % 7);
    float freq = exp2f(-(float)j * L2T_OVER16);
    float ang  = pos * freq;
    float cs, sn;
    sincosf(ang, &sn, &cs);

    float2* p = (float2*)(g_qkv + r * QKVN + which * 512 + h * 64 + 2 * m);
    float2 v = *p;
    p->x = v.x * cs - v.y * sn;
    p->y = v.x * sn + v.y * cs;
}

// ---------------- windowed attention ----------------
// one block per (b,g,head): 49x49 scores, softmax, @V; writes (b,n,c) layout
__global__ __launch_bounds__(256) void attn_kernel() {
    __shared__ float qs[49 * 68];
    __shared__ float ks[49 * 68];
    __shared__ float vs[49 * 64];
    __shared__ float sc[49 * 49];

    const int tid = threadIdx.x;
    const int h   = blockIdx.x & 7;
    const int bg  = blockIdx.x >> 3;

    const size_t base = (size_t)bg * S_ * QKVN + h * 64;

    // load q/k/v tiles
    for (int i = tid; i < 49 * 16; i += 256) {
        int s  = i >> 4;
        int d4 = (i & 15) * 4;
        size_t ro = base + (size_t)s * QKVN + d4;
        float4 q = *(const float4*)(g_qkv + ro);
        float4 k = *(const float4*)(g_qkv + ro + 512);
        float4 v = *(const float4*)(g_qkv + ro + 1024);
        *(float4*)&qs[s * 68 + d4] = q;
        *(float4*)&ks[s * 68 + d4] = k;
        *(float4*)&vs[s * 64 + d4] = v;
    }
    __syncthreads();

    // scores
    for (int p = tid; p < 49 * 49; p += 256) {
        int s  = p / 49;
        int tt = p - s * 49;
        const float* qp = &qs[s * 68];
        const float* kp = &ks[tt * 68];
        float acc = 0.0f;
        #pragma unroll
        for (int d = 0; d < 64; d += 4) {
            float4 a = *(const float4*)(qp + d);
            float4 b = *(const float4*)(kp + d);
            acc += a.x * b.x + a.y * b.y + a.z * b.z + a.w * b.w;
        }
        sc[p] = acc * SCALE_;
    }
    __syncthreads();

    // softmax: one warp per row
    const int warp = tid >> 5, lane = tid & 31;
    for (int row = warp; row < 49; row += 8) {
        float mx = -1e30f;
        for (int t = lane; t < 49; t += 32) mx = fmaxf(mx, sc[row * 49 + t]);
        #pragma unroll
        for (int o = 16; o > 0; o >>= 1) mx = fmaxf(mx, __shfl_xor_sync(0xffffffffu, mx, o));
        float sum = 0.0f;
        for (int t = lane; t < 49; t += 32) {
            float e = __expf(sc[row * 49 + t] - mx);
            sc[row * 49 + t] = e;
            sum += e;
        }
        #pragma unroll
        for (int o = 16; o > 0; o >>= 1) sum += __shfl_xor_sync(0xffffffffu, sum, o);
        float inv = 1.0f / sum;
        for (int t = lane; t < 49; t += 32) sc[row * 49 + t] *= inv;
    }
    __syncthreads();

    // out = attn @ v, scattered back to (b, n, c)
    const int g = bg & 63;
    const int b = bg >> 6;
    for (int o = tid; o < 49 * 64; o += 256) {
        int s = o >> 6;
        int d = o & 63;
        const float* sr = &sc[s * 49];
        float acc = 0.0f;
        #pragma unroll
        for (int tt = 0; tt < 49; tt++)
            acc = fmaf(sr[tt], vs[tt * 64 + d], acc);
        int sy = s / 7, sx = s - sy * 7;
        int n  = ((g >> 3) * 7 + sy) * 56 + (g & 7) * 7 + sx;
        g_att[((size_t)(b * NTOK + n)) * C_ + h * 64 + d] = acc;
    }
}

// ---------------- launch ----------------
extern "C" void kernel_launch(void* const* d_in, const int* in_sizes, int n_in,
                              void* d_out, int out_size)
{
    const float* x      = (const float*)d_in[0];
    const float* w_qkv  = (const float*)d_in[1];
    const float* w_proj = (const float*)d_in[2];
    const float* b_proj = (const float*)d_in[3];
    float* out = (float*)d_out;

    void* qkvp = nullptr;
    void* attp = nullptr;
    cudaGetSymbolAddress(&qkvp, g_qkv);
    cudaGetSymbolAddress(&attp, g_att);

    // 1) QKV GEMM with window-gather rows
    dim3 g1(M_ / 128, QKVN / 128);
    sgemm128<QKVN, true, false><<<g1, 256>>>(x, w_qkv, nullptr, (float*)qkvp);

    // 2) RoPE on q,k
    rope_kernel<<<M_ * 2, 256>>>();

    // 3) windowed attention (one block per b,g,head)
    attn_kernel<<<B_ * G_ * NH, 256>>>();

    // 4) projection GEMM + bias, writes final (b,n,d)
    dim3 g2(M_ / 128, C_ / 128);
    sgemm128<C_, false, true><<<g2, 256>>>((const float*)attp, w_proj, b_proj, out);
}

// round 3
// speedup vs baseline: 1.6447x; 1.6447x over previous
#include <cuda_runtime.h>
#include <cuda_bf16.h>
#include <cstdint>
#include <cstddef>

// ---------------- problem constants ----------------
#define B_    32
#define NTOK  3136
#define C_    512
#define NH    8
#define S_    49
#define G_    64
#define M_    (B_*G_*S_)    // 100352 (784*128)
#define QKVN  1536
#define SCALE_ 0.125f
#define L2T_OVER16 0.8304820237218406f

// ---------------- scratch ----------------
__device__ float g_qkv[(size_t)M_ * QKVN];           // fp32 qkv, (b,g,s) rows
__device__ __nv_bfloat16 g_xhi[(size_t)M_ * C_];     // gathered x, split
__device__ __nv_bfloat16 g_xlo[(size_t)M_ * C_];
__device__ __nv_bfloat16 g_whi[QKVN * C_];
__device__ __nv_bfloat16 g_wlo[QKVN * C_];
__device__ __nv_bfloat16 g_phi[C_ * C_];
__device__ __nv_bfloat16 g_plo[C_ * C_];
__device__ __nv_bfloat16 g_ahi[(size_t)M_ * C_];     // attention out, split, (b,n) rows
__device__ __nv_bfloat16 g_alo[(size_t)M_ * C_];

// row r (in b,g,s order) -> x row offset (b,n)
__device__ __forceinline__ size_t gather_row_off(int r) {
    int b   = r / (G_ * S_);
    int rem = r - b * (G_ * S_);
    int g   = rem / S_;
    int s   = rem - g * S_;
    int sy  = s / 7;
    int sx  = s - sy * 7;
    int n   = ((g >> 3) * 7 + sy) * 56 + (g & 7) * 7 + sx;
    return ((size_t)b * NTOK + n) * C_;
}

// ---------------- asm wrappers (all sm_80-generic) ----------------
__device__ __forceinline__ uint32_t smem_u32(const void* p) {
    uint32_t a;
    asm("{ .reg .u64 t; cvta.to.shared.u64 t, %1; cvt.u32.u64 %0, t; }" : "=r"(a) : "l"(p));
    return a;
}
__device__ __forceinline__ void cp16(uint32_t saddr, const void* g) {
    asm volatile("cp.async.cg.shared.global [%0], [%1], 16;" :: "r"(saddr), "l"(g));
}
__device__ __forceinline__ void cp_commit() {
    asm volatile("cp.async.commit_group;" ::: "memory");
}
__device__ __forceinline__ void cp_wait0() {
    asm volatile("cp.async.wait_group 0;" ::: "memory");
}
__device__ __forceinline__ void ldm4(uint32_t* r, uint32_t addr) {
    asm volatile("ldmatrix.sync.aligned.m8n8.x4.shared.b16 {%0,%1,%2,%3}, [%4];"
        : "=r"(r[0]), "=r"(r[1]), "=r"(r[2]), "=r"(r[3]) : "r"(addr));
}
__device__ __forceinline__ void mma16816(float* c, const uint32_t* a, const uint32_t* b) {
    asm volatile("mma.sync.aligned.m16n8k16.row.col.f32.bf16.bf16.f32 "
        "{%0,%1,%2,%3}, {%4,%5,%6,%7}, {%8,%9}, {%0,%1,%2,%3};"
        : "+f"(c[0]), "+f"(c[1]), "+f"(c[2]), "+f"(c[3])
        : "r"(a[0]), "r"(a[1]), "r"(a[2]), "r"(a[3]), "r"(b[0]), "r"(b[1]));
}

// ---------------- conversion kernels ----------------
__global__ __launch_bounds__(256) void conv_x_kernel(const float* __restrict__ x) {
    int idx = blockIdx.x * 256 + threadIdx.x;       // M_*128 threads
    int r = idx >> 7;
    int q = (idx & 127) << 2;
    float4 v = *(const float4*)(x + gather_row_off(r) + q);
    float vv[4] = {v.x, v.y, v.z, v.w};
    uint32_t hp[2], lp[2];
    #pragma unroll
    for (int p = 0; p < 2; p++) {
        __nv_bfloat162 h2, l2;
        h2.x = __float2bfloat16_rn(vv[2*p]);
        h2.y = __float2bfloat16_rn(vv[2*p+1]);
        l2.x = __float2bfloat16_rn(vv[2*p]   - __bfloat162float(h2.x));
        l2.y = __float2bfloat16_rn(vv[2*p+1] - __bfloat162float(h2.y));
        hp[p] = *(uint32_t*)&h2;
        lp[p] = *(uint32_t*)&l2;
    }
    size_t o = (size_t)r * C_ + q;
    *(uint2*)(g_xhi + o) = make_uint2(hp[0], hp[1]);
    *(uint2*)(g_xlo + o) = make_uint2(lp[0], lp[1]);
}

__global__ __launch_bounds__(256) void conv_w_kernel(const float* __restrict__ w,
                                                     __nv_bfloat16* __restrict__ hi,
                                                     __nv_bfloat16* __restrict__ lo) {
    int idx = blockIdx.x * 256 + threadIdx.x;       // rows*128 threads
    size_t o = (size_t)idx << 2;
    float4 v = *(const float4*)(w + o);
    float vv[4] = {v.x, v.y, v.z, v.w};
    uint32_t hp[2], lp[2];
    #pragma unroll
    for (int p = 0; p < 2; p++) {
        __nv_bfloat162 h2, l2;
        h2.x = __float2bfloat16_rn(vv[2*p]);
        h2.y = __float2bfloat16_rn(vv[2*p+1]);
        l2.x = __float2bfloat16_rn(vv[2*p]   - __bfloat162float(h2.x));
        l2.y = __float2bfloat16_rn(vv[2*p+1] - __bfloat162float(h2.y));
        hp[p] = *(uint32_t*)&h2;
        lp[p] = *(uint32_t*)&l2;
    }
    *(uint2*)(hi + o) = make_uint2(hp[0], hp[1]);
    *(uint2*)(lo + o) = make_uint2(lp[0], lp[1]);
}

// ---------------- split-bf16 HMMA GEMM ----------------
// C[r][d] = sum_k A[r][k]*B[d][k] (+bias), A=Ahi+Alo, B=Bhi+Blo, K=512
// block 128x128, 8 warps (2x4), warp tile 64x32, BK=64, double-buffered cp.async
#define STG_BYTES 65536u   // per stage: 4 matrices x 128 rows x 128B
#define DYN_SMEM  (2 * STG_BYTES)

template <int NCOLS, bool BIAS>
__global__ __launch_bounds__(256) void mma_gemm(
    const __nv_bfloat16* __restrict__ Ahi, const __nv_bfloat16* __restrict__ Alo,
    const __nv_bfloat16* __restrict__ Bhi, const __nv_bfloat16* __restrict__ Blo,
    const float* __restrict__ bias, float* __restrict__ Cc)
{
    extern __shared__ __align__(1024) char dyn[];
    const uint32_t sbase = smem_u32(dyn);

    const int tid  = threadIdx.x;
    const int lane = tid & 31;
    const int wid  = tid >> 5;
    const int wm   = wid >> 2;          // 0..1
    const int wn   = wid & 3;           // 0..3
    const int bm   = blockIdx.y * 128;
    const int bn   = blockIdx.x * 128;

    // ---- loader mapping: 4 groups of 64 threads, one matrix each ----
    const int grp  = tid >> 6;          // 0:Ahi 1:Alo 2:Bhi 3:Blo
    const int row0 = (tid & 63) << 1;   // 2 rows per thread
    const __nv_bfloat16* gsrc;
    if      (grp == 0) gsrc = Ahi + (size_t)bm * C_;
    else if (grp == 1) gsrc = Alo + (size_t)bm * C_;
    else if (grp == 2) gsrc = Bhi + (size_t)bn * C_;
    else               gsrc = Blo + (size_t)bn * C_;
    const uint32_t smat = sbase + grp * 16384u;

    auto load_stage = [&](int st, int kc) {
        #pragma unroll
        for (int rr = 0; rr < 2; rr++) {
            int row = row0 + rr;
            const char* gp = (const char*)(gsrc + (size_t)row * C_ + kc * 64);
            uint32_t rbase = smat + st * STG_BYTES + row * 128;
            int rx = row & 7;
            #pragma unroll
            for (int c = 0; c < 8; c++)
                cp16(rbase + (uint32_t)((c ^ rx) << 4), gp + c * 16);
        }
    };

    // ---- fragment address components ----
    const int a_r  = wm * 64 + (lane & 15);
    const int a_cp = lane >> 4;                       // chunk parity for A
    const int b_r0 = wn * 32 + (lane & 7) + ((lane & 16) >> 1);
    const int b_cp = (lane >> 3) & 1;

    float acc[4][4][4];
    #pragma unroll
    for (int i = 0; i < 4; i++)
        #pragma unroll
        for (int j = 0; j < 4; j++)
            #pragma unroll
            for (int p = 0; p < 4; p++) acc[i][j][p] = 0.0f;

    load_stage(0, 0);
    cp_commit();

    #pragma unroll 1
    for (int kc = 0; kc < 8; kc++) {
        cp_wait0();
        __syncthreads();
        if (kc < 7) { load_stage((kc + 1) & 1, kc + 1); cp_commit(); }

        const uint32_t base = sbase + (uint32_t)(kc & 1) * STG_BYTES;
        #pragma unroll
        for (int ks = 0; ks < 4; ks++) {
            uint32_t ah[4][4], al[4][4], bh[2][4], bl[2][4];
            #pragma unroll
            for (int i = 0; i < 4; i++) {
                int r  = a_r + i * 16;
                int ch = 2 * ks + a_cp;
                uint32_t ad = base + (uint32_t)(r * 128 + ((ch ^ (r & 7)) << 4));
                ldm4(ah[i], ad);
                ldm4(al[i], ad + 16384u);
            }
            #pragma unroll
            for (int jj = 0; jj < 2; jj++) {
                int r  = b_r0 + jj * 16;
                int ch = 2 * ks + b_cp;
                uint32_t ad = base + 32768u + (uint32_t)(r * 128 + ((ch ^ (r & 7)) << 4));
                ldm4(bh[jj], ad);
                ldm4(bl[jj], ad + 16384u);
            }
            #pragma unroll
            for (int i = 0; i < 4; i++)
                #pragma unroll
                for (int j = 0; j < 4; j++) {
                    const uint32_t* bhp = &bh[j >> 1][(j & 1) * 2];
                    const uint32_t* blp = &bl[j >> 1][(j & 1) * 2];
                    mma16816(acc[i][j], ah[i], bhp);
                    mma16816(acc[i][j], al[i], bhp);
                    mma16816(acc[i][j], ah[i], blp);
                }
        }
        __syncthreads();
    }

    // ---- epilogue ----
    const int orow = bm + wm * 64 + (lane >> 2);
    const int ocol = bn + wn * 32 + (lane & 3) * 2;
    #pragma unroll
    for (int i = 0; i < 4; i++) {
        #pragma unroll
        for (int j = 0; j < 4; j++) {
            int rr = orow + i * 16;
            int cc = ocol + j * 8;
            float bx = 0.f, by = 0.f;
            if (BIAS) { bx = bias[cc]; by = bias[cc + 1]; }
            float2 o0 = make_float2(acc[i][j][0] + bx, acc[i][j][1] + by);
            float2 o1 = make_float2(acc[i][j][2] + bx, acc[i][j][3] + by);
            *(float2*)(Cc + (size_t)rr * NCOLS + cc)       = o0;
            *(float2*)(Cc + (size_t)(rr + 8) * NCOLS + cc) = o1;
        }
    }
}

// ---------------- 2D RoPE on q and k ----------------
__global__ __launch_bounds__(256) void rope_kernel() {
    size_t t = (size_t)blockIdx.x * 256 + threadIdx.x;
    int m     = (int)(t & 31);
    int h     = (int)((t >> 5) & 7);
    int which = (int)((t >> 8) & 1);
    size_t r  = t >> 9;
    int s     = (int)(r % S_);

    int   j    = m >> 1;
    float pos  = (m & 1) ? (float)(s / 7) : (float)(s % 7);
    float freq = exp2f(-(float)j * L2T_OVER16);
    float ang  = pos * freq;
    float cs, sn;
    sincosf(ang, &sn, &cs);

    float2* p = (float2*)(g_qkv + r * QKVN + which * 512 + h * 64 + 2 * m);
    float2 v = *p;
    p->x = v.x * cs - v.y * sn;
    p->y = v.x * sn + v.y * cs;
}

// ---------------- windowed attention (writes split bf16) ----------------
__global__ __launch_bounds__(256) void attn_kernel() {
    __shared__ float qs[49 * 68];
    __shared__ float ks[49 * 68];
    __shared__ float vs[49 * 64];
    __shared__ float sc[49 * 49];

    const int tid = threadIdx.x;
    const int h   = blockIdx.x & 7;
    const int bg  = blockIdx.x >> 3;

    const size_t base = (size_t)bg * S_ * QKVN + h * 64;

    for (int i = tid; i < 49 * 16; i += 256) {
        int s  = i >> 4;
        int d4 = (i & 15) * 4;
        size_t ro = base + (size_t)s * QKVN + d4;
        float4 q = *(const float4*)(g_qkv + ro);
        float4 k = *(const float4*)(g_qkv + ro + 512);
        float4 v = *(const float4*)(g_qkv + ro + 1024);
        *(float4*)&qs[s * 68 + d4] = q;
        *(float4*)&ks[s * 68 + d4] = k;
        *(float4*)&vs[s * 64 + d4] = v;
    }
    __syncthreads();

    for (int p = tid; p < 49 * 49; p += 256) {
        int s  = p / 49;
        int tt = p - s * 49;
        const float* qp = &qs[s * 68];
        const float* kp = &ks[tt * 68];
        float acc = 0.0f;
        #pragma unroll
        for (int d = 0; d < 64; d += 4) {
            float4 a = *(const float4*)(qp + d);
            float4 b = *(const float4*)(kp + d);
            acc += a.x * b.x + a.y * b.y + a.z * b.z + a.w * b.w;
        }
        sc[p] = acc * SCALE_;
    }
    __syncthreads();

    const int warp = tid >> 5, lane = tid & 31;
    for (int row = warp; row < 49; row += 8) {
        float mx = -1e30f;
        for (int t = lane; t < 49; t += 32) mx = fmaxf(mx, sc[row * 49 + t]);
        #pragma unroll
        for (int o = 16; o > 0; o >>= 1) mx = fmaxf(mx, __shfl_xor_sync(0xffffffffu, mx, o));
        float sum = 0.0f;
        for (int t = lane; t < 49; t += 32) {
            float e = __expf(sc[row * 49 + t] - mx);
            sc[row * 49 + t] = e;
            sum += e;
        }
        #pragma unroll
        for (int o = 16; o > 0; o >>= 1) sum += __shfl_xor_sync(0xffffffffu, sum, o);
        float inv = 1.0f / sum;
        for (int t = lane; t < 49; t += 32) sc[row * 49 + t] *= inv;
    }
    __syncthreads();

    const int g = bg & 63;
    const int b = bg >> 6;
    for (int o = tid; o < 49 * 64; o += 256) {
        int s = o >> 6;
        int d = o & 63;
        const float* sr = &sc[s * 49];
        float acc = 0.0f;
        #pragma unroll
        for (int tt = 0; tt < 49; tt++)
            acc = fmaf(sr[tt], vs[tt * 64 + d], acc);
        int sy = s / 7, sx = s - sy * 7;
        int n  = ((g >> 3) * 7 + sy) * 56 + (g & 7) * 7 + sx;
        size_t off = ((size_t)(b * NTOK + n)) * C_ + h * 64 + d;
        __nv_bfloat16 hv = __float2bfloat16_rn(acc);
        g_ahi[off] = hv;
        g_alo[off] = __float2bfloat16_rn(acc - __bfloat162float(hv));
    }
}

// ---------------- launch ----------------
extern "C" void kernel_launch(void* const* d_in, const int* in_sizes, int n_in,
                              void* d_out, int out_size)
{
    const float* x      = (const float*)d_in[0];
    const float* w_qkv  = (const float*)d_in[1];
    const float* w_proj = (const float*)d_in[2];
    const float* b_proj = (const float*)d_in[3];
    float* out = (float*)d_out;

    void *qkvp, *xhip, *xlop, *whip, *wlop, *phip, *plop, *ahip, *alop;
    cudaGetSymbolAddress(&qkvp, g_qkv);
    cudaGetSymbolAddress(&xhip, g_xhi); cudaGetSymbolAddress(&xlop, g_xlo);
    cudaGetSymbolAddress(&whip, g_whi); cudaGetSymbolAddress(&wlop, g_wlo);
    cudaGetSymbolAddress(&phip, g_phi); cudaGetSymbolAddress(&plop, g_plo);
    cudaGetSymbolAddress(&ahip, g_ahi); cudaGetSymbolAddress(&alop, g_alo);

    cudaFuncSetAttribute(mma_gemm<QKVN, false>,
                         cudaFuncAttributeMaxDynamicSharedMemorySize, DYN_SMEM);
    cudaFuncSetAttribute(mma_gemm<C_, true>,
                         cudaFuncAttributeMaxDynamicSharedMemorySize, DYN_SMEM);

    // 0) conversions
    conv_x_kernel<<<M_ * 128 / 256, 256>>>(x);
    conv_w_kernel<<<QKVN * 128 / 256, 256>>>(w_qkv, (__nv_bfloat16*)whip, (__nv_bfloat16*)wlop);
    conv_w_kernel<<<C_ * 128 / 256, 256>>>(w_proj, (__nv_bfloat16*)phip, (__nv_bfloat16*)plop);

    // 1) QKV GEMM (split-bf16 HMMA)
    dim3 g1(QKVN / 128, M_ / 128);
    mma_gemm<QKVN, false><<<g1, 256, DYN_SMEM>>>(
        (const __nv_bfloat16*)xhip, (const __nv_bfloat16*)xlop,
        (const __nv_bfloat16*)whip, (const __nv_bfloat16*)wlop,
        nullptr, (float*)qkvp);

    // 2) RoPE
    rope_kernel<<<M_ * 2, 256>>>();

    // 3) windowed attention
    attn_kernel<<<B_ * G_ * NH, 256>>>();

    // 4) projection GEMM + bias
    dim3 g2(C_ / 128, M_ / 128);
    mma_gemm<C_, true><<<g2, 256, DYN_SMEM>>>(
        (const __nv_bfloat16*)ahip, (const __nv_bfloat16*)alop,
        (const __nv_bfloat16*)phip, (const __nv_bfloat16*)plop,
        b_proj, out);
}

// round 4
// speedup vs baseline: 1.8845x; 1.1458x over previous
#include <cuda_runtime.h>
#include <cuda_bf16.h>
#include <cstdint>
#include <cstddef>

// ---------------- problem constants ----------------
#define B_    32
#define NTOK  3136
#define C_    512
#define NH    8
#define S_    49
#define G_    64
#define M_    (B_*G_*S_)    // 100352 (784*128)
#define QKVN  1536
#define SCALE_ 0.125f
#define L2T_OVER16 0.8304820237218406f

// ---------------- scratch ----------------
__device__ float g_qkv[(size_t)M_ * QKVN];           // fp32 qkv (roped), (b,g,s) rows
__device__ __nv_bfloat16 g_xhi[(size_t)M_ * C_];     // gathered x, split
__device__ __nv_bfloat16 g_xlo[(size_t)M_ * C_];
__device__ __nv_bfloat16 g_whi[QKVN * C_];
__device__ __nv_bfloat16 g_wlo[QKVN * C_];
__device__ __nv_bfloat16 g_phi[C_ * C_];
__device__ __nv_bfloat16 g_plo[C_ * C_];
__device__ __nv_bfloat16 g_ahi[(size_t)M_ * C_];     // attention out, split, (b,n) rows
__device__ __nv_bfloat16 g_alo[(size_t)M_ * C_];

// row r (in b,g,s order) -> x row offset (b,n)
__device__ __forceinline__ size_t gather_row_off(int r) {
    int b   = r / (G_ * S_);
    int rem = r - b * (G_ * S_);
    int g   = rem / S_;
    int s   = rem - g * S_;
    int sy  = s / 7;
    int sx  = s - sy * 7;
    int n   = ((g >> 3) * 7 + sy) * 56 + (g & 7) * 7 + sx;
    return ((size_t)b * NTOK + n) * C_;
}

// ---------------- asm wrappers ----------------
__device__ __forceinline__ uint32_t smem_u32(const void* p) {
    uint32_t a;
    asm("{ .reg .u64 t; cvta.to.shared.u64 t, %1; cvt.u32.u64 %0, t; }" : "=r"(a) : "l"(p));
    return a;
}
__device__ __forceinline__ void cp16(uint32_t saddr, const void* g) {
    asm volatile("cp.async.cg.shared.global [%0], [%1], 16;" :: "r"(saddr), "l"(g));
}
__device__ __forceinline__ void cp_commit() {
    asm volatile("cp.async.commit_group;" ::: "memory");
}
__device__ __forceinline__ void cp_wait0() {
    asm volatile("cp.async.wait_group 0;" ::: "memory");
}
__device__ __forceinline__ void cp_wait1() {
    asm volatile("cp.async.wait_group 1;" ::: "memory");
}
__device__ __forceinline__ void ldm4(uint32_t* r, uint32_t addr) {
    asm volatile("ldmatrix.sync.aligned.m8n8.x4.shared.b16 {%0,%1,%2,%3}, [%4];"
        : "=r"(r[0]), "=r"(r[1]), "=r"(r[2]), "=r"(r[3]) : "r"(addr));
}
__device__ __forceinline__ void mma16816(float* c, const uint32_t* a, const uint32_t* b) {
    asm volatile("mma.sync.aligned.m16n8k16.row.col.f32.bf16.bf16.f32 "
        "{%0,%1,%2,%3}, {%4,%5,%6,%7}, {%8,%9}, {%0,%1,%2,%3};"
        : "+f"(c[0]), "+f"(c[1]), "+f"(c[2]), "+f"(c[3])
        : "r"(a[0]), "r"(a[1]), "r"(a[2]), "r"(a[3]), "r"(b[0]), "r"(b[1]));
}

// ---------------- conversion kernels ----------------
__global__ __launch_bounds__(256) void conv_x_kernel(const float* __restrict__ x) {
    int idx = blockIdx.x * 256 + threadIdx.x;       // M_*128 threads
    int r = idx >> 7;
    int q = (idx & 127) << 2;
    float4 v = *(const float4*)(x + gather_row_off(r) + q);
    float vv[4] = {v.x, v.y, v.z, v.w};
    uint32_t hp[2], lp[2];
    #pragma unroll
    for (int p = 0; p < 2; p++) {
        __nv_bfloat162 h2, l2;
        h2.x = __float2bfloat16_rn(vv[2*p]);
        h2.y = __float2bfloat16_rn(vv[2*p+1]);
        l2.x = __float2bfloat16_rn(vv[2*p]   - __bfloat162float(h2.x));
        l2.y = __float2bfloat16_rn(vv[2*p+1] - __bfloat162float(h2.y));
        hp[p] = *(uint32_t*)&h2;
        lp[p] = *(uint32_t*)&l2;
    }
    size_t o = (size_t)r * C_ + q;
    *(uint2*)(g_xhi + o) = make_uint2(hp[0], hp[1]);
    *(uint2*)(g_xlo + o) = make_uint2(lp[0], lp[1]);
}

__global__ __launch_bounds__(256) void conv_w_kernel(const float* __restrict__ w,
                                                     __nv_bfloat16* __restrict__ hi,
                                                     __nv_bfloat16* __restrict__ lo) {
    int idx = blockIdx.x * 256 + threadIdx.x;
    size_t o = (size_t)idx << 2;
    float4 v = *(const float4*)(w + o);
    float vv[4] = {v.x, v.y, v.z, v.w};
    uint32_t hp[2], lp[2];
    #pragma unroll
    for (int p = 0; p < 2; p++) {
        __nv_bfloat162 h2, l2;
        h2.x = __float2bfloat16_rn(vv[2*p]);
        h2.y = __float2bfloat16_rn(vv[2*p+1]);
        l2.x = __float2bfloat16_rn(vv[2*p]   - __bfloat162float(h2.x));
        l2.y = __float2bfloat16_rn(vv[2*p+1] - __bfloat162float(h2.y));
        hp[p] = *(uint32_t*)&h2;
        lp[p] = *(uint32_t*)&l2;
    }
    *(uint2*)(hi + o) = make_uint2(hp[0], hp[1]);
    *(uint2*)(lo + o) = make_uint2(lp[0], lp[1]);
}

// ---------------- split-bf16 HMMA GEMM ----------------
// C[r][d] = sum_k A[r][k]*B[d][k] (+bias / +rope), K=512
// block 128x128, 8 warps (2x4), warp tile 64x32, BK=32, 3-stage cp.async
// Tiles stored row-paired: 2 logical rows (64B each) per 128B physical row,
// SW128 xor swizzle on physical rows.
#define STG_BYTES 32768u   // 4 matrices x 64 phys rows x 128B
#define NSTG 3
#define DYN_SMEM (NSTG * STG_BYTES)

template <int NCOLS, bool BIAS, bool ROPE>
__global__ __launch_bounds__(256, 2) void mma_gemm(
    const __nv_bfloat16* __restrict__ Ahi, const __nv_bfloat16* __restrict__ Alo,
    const __nv_bfloat16* __restrict__ Bhi, const __nv_bfloat16* __restrict__ Blo,
    const float* __restrict__ bias, float* __restrict__ Cc)
{
    extern __shared__ __align__(1024) char dyn[];
    const uint32_t sbase = smem_u32(dyn);

    const int tid  = threadIdx.x;
    const int lane = tid & 31;
    const int wid  = tid >> 5;
    const int wm   = wid >> 2;          // 0..1
    const int wn   = wid & 3;           // 0..3
    const int bm   = blockIdx.y * 128;
    const int bn   = blockIdx.x * 128;

    // ---- loader: 4 groups of 64 threads, one matrix each; 1 phys row/thread ----
    const int grp  = tid >> 6;          // 0:Ahi 1:Alo 2:Bhi 3:Blo
    const int prow = tid & 63;
    const __nv_bfloat16* gsrc;
    if      (grp == 0) gsrc = Ahi + (size_t)bm * C_;
    else if (grp == 1) gsrc = Alo + (size_t)bm * C_;
    else if (grp == 2) gsrc = Bhi + (size_t)bn * C_;
    else               gsrc = Blo + (size_t)bn * C_;
    const __nv_bfloat16* grow = gsrc + (size_t)(2 * prow) * C_;
    const uint32_t smat = sbase + grp * 8192u + prow * 128u;
    const int sx = prow & 7;

    auto load_stage = [&](int st, int kc) {
        const char* g0 = (const char*)(grow + kc * 32);
        uint32_t rb = smat + (uint32_t)st * STG_BYTES;
        #pragma unroll
        for (int c = 0; c < 8; c++)
            cp16(rb + (uint32_t)((c ^ sx) << 4), g0 + (c >> 2) * (C_ * 2) + (c & 3) * 16);
    };

    // ---- fragment address components ----
    const int a_r  = wm * 64 + (lane & 15);
    const int a_cp = lane >> 4;
    const int b_r0 = wn * 32 + (lane & 7) + ((lane & 16) >> 1);
    const int b_cp = (lane >> 3) & 1;

    float acc[4][4][4];
    #pragma unroll
    for (int i = 0; i < 4; i++)
        #pragma unroll
        for (int j = 0; j < 4; j++)
            #pragma unroll
            for (int p = 0; p < 4; p++) acc[i][j][p] = 0.0f;

    load_stage(0, 0); cp_commit();
    load_stage(1, 1); cp_commit();

    #pragma unroll 1
    for (int kc = 0; kc < 16; kc++) {
        if (kc < 15) cp_wait1(); else cp_wait0();
        __syncthreads();
        if (kc + 2 < 16) { load_stage((kc + 2) % NSTG, kc + 2); cp_commit(); }

        const uint32_t base = sbase + (uint32_t)(kc % NSTG) * STG_BYTES;
        #pragma unroll
        for (int ks = 0; ks < 2; ks++) {
            uint32_t ah[4][4], al[4][4], bh[2][4], bl[2][4];
            const int ch4 = 2 * ks;
            #pragma unroll
            for (int i = 0; i < 4; i++) {
                int r  = a_r + i * 16;
                int pr = r >> 1;
                int pc = ((r & 1) << 2) + ch4 + a_cp;
                uint32_t ad = base + (uint32_t)(pr * 128 + ((pc ^ (pr & 7)) << 4));
                ldm4(ah[i], ad);
                ldm4(al[i], ad + 8192u);
            }
            #pragma unroll
            for (int jj = 0; jj < 2; jj++) {
                int r  = b_r0 + jj * 16;
                int pr = r >> 1;
                int pc = ((r & 1) << 2) + ch4 + b_cp;
                uint32_t ad = base + 16384u + (uint32_t)(pr * 128 + ((pc ^ (pr & 7)) << 4));
                ldm4(bh[jj], ad);
                ldm4(bl[jj], ad + 8192u);
            }
            #pragma unroll
            for (int i = 0; i < 4; i++)
                #pragma unroll
                for (int j = 0; j < 4; j++) {
                    const uint32_t* bhp = &bh[j >> 1][(j & 1) * 2];
                    const uint32_t* blp = &bl[j >> 1][(j & 1) * 2];
                    mma16816(acc[i][j], ah[i], bhp);
                    mma16816(acc[i][j], al[i], bhp);
                    mma16816(acc[i][j], ah[i], blp);
                }
        }
        __syncthreads();
    }

    // ---- epilogue (optionally fused 2D RoPE) ----
    const int orow = bm + wm * 64 + (lane >> 2);
    const int ocol = bn + wn * 32 + (lane & 3) * 2;
    #pragma unroll
    for (int i = 0; i < 4; i++) {
        const int rA = orow + i * 16;
        const int rB = rA + 8;
        int sA = 0, sB = 0;
        if (ROPE) { sA = rA % S_; sB = rB % S_; }
        #pragma unroll
        for (int j = 0; j < 4; j++) {
            const int cc = ocol + j * 8;
            float v0 = acc[i][j][0], v1 = acc[i][j][1];
            float v2 = acc[i][j][2], v3 = acc[i][j][3];
            if (ROPE && cc < 1024) {
                int m = (cc & 63) >> 1;
                float freq = exp2f(-(float)(m >> 1) * L2T_OVER16);
                float pA = (m & 1) ? (float)(sA / 7) : (float)(sA % 7);
                float pB = (m & 1) ? (float)(sB / 7) : (float)(sB % 7);
                float snA, csA, snB, csB;
                sincosf(pA * freq, &snA, &csA);
                sincosf(pB * freq, &snB, &csB);
                float t0 = v0 * csA - v1 * snA, t1 = v0 * snA + v1 * csA;
                float t2 = v2 * csB - v3 * snB, t3 = v2 * snB + v3 * csB;
                v0 = t0; v1 = t1; v2 = t2; v3 = t3;
            }
            if (BIAS) {
                float bx = bias[cc], by = bias[cc + 1];
                v0 += bx; v1 += by; v2 += bx; v3 += by;
            }
            *(float2*)(Cc + (size_t)rA * NCOLS + cc) = make_float2(v0, v1);
            *(float2*)(Cc + (size_t)rB * NCOLS + cc) = make_float2(v2, v3);
        }
    }
}

// ---------------- windowed attention (writes split bf16) ----------------
__global__ __launch_bounds__(256) void attn_kernel() {
    __shared__ float qs[49 * 68];
    __shared__ float ks[49 * 68];
    __shared__ float vs[49 * 64];
    __shared__ float sc[49 * 49];

    const int tid = threadIdx.x;
    const int h   = blockIdx.x & 7;
    const int bg  = blockIdx.x >> 3;

    const size_t base = (size_t)bg * S_ * QKVN + h * 64;

    for (int i = tid; i < 49 * 16; i += 256) {
        int s  = i >> 4;
        int d4 = (i & 15) * 4;
        size_t ro = base + (size_t)s * QKVN + d4;
        float4 q = *(const float4*)(g_qkv + ro);
        float4 k = *(const float4*)(g_qkv + ro + 512);
        float4 v = *(const float4*)(g_qkv + ro + 1024);
        *(float4*)&qs[s * 68 + d4] = q;
        *(float4*)&ks[s * 68 + d4] = k;
        *(float4*)&vs[s * 64 + d4] = v;
    }
    __syncthreads();

    for (int p = tid; p < 49 * 49; p += 256) {
        int s  = p / 49;
        int tt = p - s * 49;
        const float* qp = &qs[s * 68];
        const float* kp = &ks[tt * 68];
        float acc = 0.0f;
        #pragma unroll
        for (int d = 0; d < 64; d += 4) {
            float4 a = *(const float4*)(qp + d);
            float4 b = *(const float4*)(kp + d);
            acc += a.x * b.x + a.y * b.y + a.z * b.z + a.w * b.w;
        }
        sc[p] = acc * SCALE_;
    }
    __syncthreads();

    const int warp = tid >> 5, lane = tid & 31;
    for (int row = warp; row < 49; row += 8) {
        float mx = -1e30f;
        for (int t = lane; t < 49; t += 32) mx = fmaxf(mx, sc[row * 49 + t]);
        #pragma unroll
        for (int o = 16; o > 0; o >>= 1) mx = fmaxf(mx, __shfl_xor_sync(0xffffffffu, mx, o));
        float sum = 0.0f;
        for (int t = lane; t < 49; t += 32) {
            float e = __expf(sc[row * 49 + t] - mx);
            sc[row * 49 + t] = e;
            sum += e;
        }
        #pragma unroll
        for (int o = 16; o > 0; o >>= 1) sum += __shfl_xor_sync(0xffffffffu, sum, o);
        float inv = 1.0f / sum;
        for (int t = lane; t < 49; t += 32) sc[row * 49 + t] *= inv;
    }
    __syncthreads();

    const int g = bg & 63;
    const int b = bg >> 6;
    for (int o = tid; o < 49 * 64; o += 256) {
        int s = o >> 6;
        int d = o & 63;
        const float* sr = &sc[s * 49];
        float acc = 0.0f;
        #pragma unroll
        for (int tt = 0; tt < 49; tt++)
            acc = fmaf(sr[tt], vs[tt * 64 + d], acc);
        int sy = s / 7, sx = s - sy * 7;
        int n  = ((g >> 3) * 7 + sy) * 56 + (g & 7) * 7 + sx;
        size_t off = ((size_t)(b * NTOK + n)) * C_ + h * 64 + d;
        __nv_bfloat16 hv = __float2bfloat16_rn(acc);
        g_ahi[off] = hv;
        g_alo[off] = __float2bfloat16_rn(acc - __bfloat162float(hv));
    }
}

// ---------------- launch ----------------
extern "C" void kernel_launch(void* const* d_in, const int* in_sizes, int n_in,
                              void* d_out, int out_size)
{
    const float* x      = (const float*)d_in[0];
    const float* w_qkv  = (const float*)d_in[1];
    const float* w_proj = (const float*)d_in[2];
    const float* b_proj = (const float*)d_in[3];
    float* out = (float*)d_out;

    void *qkvp, *xhip, *xlop, *whip, *wlop, *phip, *plop, *ahip, *alop;
    cudaGetSymbolAddress(&qkvp, g_qkv);
    cudaGetSymbolAddress(&xhip, g_xhi); cudaGetSymbolAddress(&xlop, g_xlo);
    cudaGetSymbolAddress(&whip, g_whi); cudaGetSymbolAddress(&wlop, g_wlo);
    cudaGetSymbolAddress(&phip, g_phi); cudaGetSymbolAddress(&plop, g_plo);
    cudaGetSymbolAddress(&ahip, g_ahi); cudaGetSymbolAddress(&alop, g_alo);

    cudaFuncSetAttribute(mma_gemm<QKVN, false, true>,
                         cudaFuncAttributeMaxDynamicSharedMemorySize, DYN_SMEM);
    cudaFuncSetAttribute(mma_gemm<C_, true, false>,
                         cudaFuncAttributeMaxDynamicSharedMemorySize, DYN_SMEM);

    // 0) conversions
    conv_x_kernel<<<M_ * 128 / 256, 256>>>(x);
    conv_w_kernel<<<QKVN * 128 / 256, 256>>>(w_qkv, (__nv_bfloat16*)whip, (__nv_bfloat16*)wlop);
    conv_w_kernel<<<C_ * 128 / 256, 256>>>(w_proj, (__nv_bfloat16*)phip, (__nv_bfloat16*)plop);

    // 1) QKV GEMM (split-bf16 HMMA) with fused RoPE in epilogue
    dim3 g1(QKVN / 128, M_ / 128);
    mma_gemm<QKVN, false, true><<<g1, 256, DYN_SMEM>>>(
        (const __nv_bfloat16*)xhip, (const __nv_bfloat16*)xlop,
        (const __nv_bfloat16*)whip, (const __nv_bfloat16*)wlop,
        nullptr, (float*)qkvp);

    // 2) windowed attention
    attn_kernel<<<B_ * G_ * NH, 256>>>();

    // 3) projection GEMM + bias
    dim3 g2(C_ / 128, M_ / 128);
    mma_gemm<C_, true, false><<<g2, 256, DYN_SMEM>>>(
        (const __nv_bfloat16*)ahip, (const __nv_bfloat16*)alop,
        (const __nv_bfloat16*)phip, (const __nv_bfloat16*)plop,
        b_proj, out);
}